// round 4
// baseline (speedup 1.0000x reference)
#include <cuda_runtime.h>
#include <cuda_bf16.h>
#include <cstdint>

#define BB 4
#define SS 2048
#define FF 1024
#define BS (BB*SS)

// ---------------------------------------------------------------------------
// Scratch (static device globals — no allocation)
// ---------------------------------------------------------------------------
__device__ __align__(16) __nv_bfloat16 g_qh[BS*FF],  g_ql[BS*FF];
__device__ __align__(16) __nv_bfloat16 g_kh[BS*FF],  g_kl[BS*FF];
__device__ __align__(16) __nv_bfloat16 g_vh[BS*FF],  g_vl[BS*FF];
__device__ __align__(16) __nv_bfloat16 g_wqh[FF*FF], g_wql[FF*FF];
__device__ __align__(16) __nv_bfloat16 g_wkh[FF*FF], g_wkl[FF*FF];
__device__ __align__(16) __nv_bfloat16 g_wvh[FF*FF], g_wvl[FF*FF];
__device__ __align__(16) __nv_bfloat16 g_qph[BS*FF], g_qpl[BS*FF];
__device__ __align__(16) __nv_bfloat16 g_kph[BS*FF], g_kpl[BS*FF];
__device__ __align__(16) __nv_bfloat16 g_vpth[BS*FF], g_vptl[BS*FF];   // vp^T [b][f][s]
__device__ float g_attn[BB*SS*SS];                                      // fp32 logits
__device__ __align__(16) __nv_bfloat16 g_ath[BB*SS*SS], g_atl[BB*SS*SS];

// ---------------------------------------------------------------------------
// PTX helpers (compute_103-safe: cp.async / ldmatrix / mma.sync only)
// ---------------------------------------------------------------------------
__device__ __forceinline__ uint32_t smem_u32(const void* p) {
    uint32_t a;
    asm("{ .reg .u64 t; cvta.to.shared.u64 t, %1; cvt.u32.u64 %0, t; }"
        : "=r"(a) : "l"(p));
    return a;
}

#define CP_ASYNC16(dst, src)                                                  \
    asm volatile("cp.async.cg.shared.global [%0], [%1], 16;"                  \
                 :: "r"(dst), "l"(src))
#define CP_COMMIT() asm volatile("cp.async.commit_group;" ::: "memory")
#define CP_WAIT(n)  asm volatile("cp.async.wait_group %0;" :: "n"(n) : "memory")

#define LDSM4(R, addr)                                                        \
    asm volatile("ldmatrix.sync.aligned.m8n8.x4.shared.b16 {%0,%1,%2,%3}, [%4];" \
                 : "=r"((R)[0]), "=r"((R)[1]), "=r"((R)[2]), "=r"((R)[3])     \
                 : "r"(addr))

#define MMA(D, A, B0, B1)                                                     \
    asm volatile("mma.sync.aligned.m16n8k16.row.col.f32.bf16.bf16.f32 "       \
                 "{%0,%1,%2,%3}, {%4,%5,%6,%7}, {%8,%9}, {%0,%1,%2,%3};"      \
                 : "+f"((D)[0]), "+f"((D)[1]), "+f"((D)[2]), "+f"((D)[3])     \
                 : "r"((A)[0]), "r"((A)[1]), "r"((A)[2]), "r"((A)[3]),        \
                   "r"(B0), "r"(B1))

// ---------------------------------------------------------------------------
// fp32 -> bf16 hi/lo split
// ---------------------------------------------------------------------------
__global__ __launch_bounds__(256) void split_kernel(
    const float* __restrict__ src,
    __nv_bfloat16* __restrict__ hi, __nv_bfloat16* __restrict__ lo, int n4)
{
    int i = blockIdx.x * 256 + threadIdx.x;
    if (i >= n4) return;
    float4 v = reinterpret_cast<const float4*>(src)[i];
    __nv_bfloat16 h0 = __float2bfloat16(v.x);
    __nv_bfloat16 h1 = __float2bfloat16(v.y);
    __nv_bfloat16 h2 = __float2bfloat16(v.z);
    __nv_bfloat16 h3 = __float2bfloat16(v.w);
    __nv_bfloat16 l0 = __float2bfloat16(v.x - __bfloat162float(h0));
    __nv_bfloat16 l1 = __float2bfloat16(v.y - __bfloat162float(h1));
    __nv_bfloat16 l2 = __float2bfloat16(v.z - __bfloat162float(h2));
    __nv_bfloat16 l3 = __float2bfloat16(v.w - __bfloat162float(h3));
    __nv_bfloat162* H = reinterpret_cast<__nv_bfloat162*>(hi);
    __nv_bfloat162* L = reinterpret_cast<__nv_bfloat162*>(lo);
    H[2*i]   = __halves2bfloat162(h0, h1);
    H[2*i+1] = __halves2bfloat162(h2, h3);
    L[2*i]   = __halves2bfloat162(l0, l1);
    L[2*i+1] = __halves2bfloat162(l2, l3);
}

// ---------------------------------------------------------------------------
// mma.sync split-bf16 GEMM (NT): C[m,n] = sum_k A[m,k]*B[n,k]
//   = Ah*Bh + Ah*Bl + Al*Bh   (fp32 accum in registers)
// CTA tile 128x128, BK=32, 4 warps (2 M x 2 N), warp tile 64x64.
// Double-buffered cp.async, one __syncthreads per iter, prefetch overlaps MMA.
// mode 0: outF = acc (+ residual)
// mode 1: acc + bias -> hi/lo bf16 at [m*ldc + n]
// mode 2: acc + bias -> hi/lo bf16 transposed [(b*FF+n)*SS + s], m=b*SS+s
// ---------------------------------------------------------------------------
#define PADW   40                 // padded row length in bf16 elems (80 B)
#define TILEB  (128*PADW*2)       // 10240 B per tile
#define OFF_AH 0
#define OFF_AL (1*TILEB)
#define OFF_BH (2*TILEB)
#define OFF_BL (3*TILEB)
#define STAGEB (4*TILEB)          // 40960
#define SMEMB  (2*STAGEB)         // 81920

__device__ __forceinline__ void load_stage(
    uint32_t sdst,
    const __nv_bfloat16* pAh, const __nv_bfloat16* pAl,
    const __nv_bfloat16* pBh, const __nv_bfloat16* pBl,
    int row0, int col0, int K, int k0, int tid)
{
    const int ch = tid & 3;             // 16B chunk within 64B row
    const int rb = tid >> 2;            // 0..31
#pragma unroll
    for (int tile = 0; tile < 4; ++tile) {
        const __nv_bfloat16* base =
            (tile == 0) ? pAh : (tile == 1) ? pAl : (tile == 2) ? pBh : pBl;
        const int r0 = (tile < 2) ? row0 : col0;
#pragma unroll
        for (int j = 0; j < 4; ++j) {
            const int r = rb + j * 32;
            uint32_t sm = sdst + tile * TILEB + r * (PADW*2) + ch * 16;
            CP_ASYNC16(sm, base + (long long)(r0 + r) * K + k0 + ch * 8);
        }
    }
}

__global__ __launch_bounds__(128, 2) void gemm_mma_kernel(
    const __nv_bfloat16* __restrict__ Ah, const __nv_bfloat16* __restrict__ Al,
    const __nv_bfloat16* __restrict__ Bh, const __nv_bfloat16* __restrict__ Bl,
    int K, long long sA, long long sB,
    const float* __restrict__ bias,
    const float* __restrict__ residual, long long sR,
    float* __restrict__ outF, long long sC, int ldc,
    __nv_bfloat16* __restrict__ outH, __nv_bfloat16* __restrict__ outL,
    int mode)
{
    extern __shared__ char smem[];
    const uint32_t sbase = smem_u32(smem);
    const int tid = threadIdx.x;
    const int wid = tid >> 5, lid = tid & 31;
    const int warp_m = wid & 1, warp_n = wid >> 1;   // 2x2 warps, tile 64x64
    const int row0 = blockIdx.y * 128, col0 = blockIdx.x * 128;
    const long long z = blockIdx.z;

    const __nv_bfloat16* pAh = Ah + z * sA;
    const __nv_bfloat16* pAl = Al + z * sA;
    const __nv_bfloat16* pBh = Bh + z * sB;
    const __nv_bfloat16* pBl = Bl + z * sB;

    float acc[4][8][4];
#pragma unroll
    for (int mt = 0; mt < 4; ++mt)
#pragma unroll
        for (int n = 0; n < 8; ++n)
#pragma unroll
            for (int c = 0; c < 4; ++c) acc[mt][n][c] = 0.f;

    // ldmatrix lane-address components (bytes within a tile)
    // A m16k16 quad: lanes0-7 m0-7/k0, 8-15 m8-15/k0, 16-23 m0-7/k8, 24-31 m8-15/k8
    const uint32_t a_quad = (((lid & 15)) * PADW + ((lid >> 4) * 8)) * 2;
    // B n16k16 quad: lanes0-7 n0-7/k0, 8-15 n0-7/k8, 16-23 n8-15/k0, 24-31 n8-15/k8
    const uint32_t b_quad =
        ((((lid >> 4) << 3) + (lid & 7)) * PADW + (((lid >> 3) & 1) * 8)) * 2;

    const int iters = K >> 5;
    load_stage(sbase, pAh, pAl, pBh, pBl, row0, col0, K, 0, tid);
    CP_COMMIT();

    for (int it = 0; it < iters; ++it) {
        const uint32_t buf = (it & 1) ? (sbase + STAGEB) : sbase;
        CP_WAIT(0);
        __syncthreads();
        if (it + 1 < iters) {
            const uint32_t nbuf = (it & 1) ? sbase : (sbase + STAGEB);
            load_stage(nbuf, pAh, pAl, pBh, pBl, row0, col0, K,
                       (it + 1) << 5, tid);
            CP_COMMIT();
        }

#pragma unroll
        for (int kk = 0; kk < 2; ++kk) {
            uint32_t a_h[4][4], a_l[4][4];
#pragma unroll
            for (int mt = 0; mt < 4; ++mt) {
                const uint32_t ao =
                    ((warp_m * 64 + mt * 16) * PADW + kk * 16) * 2 + a_quad;
                LDSM4(a_h[mt], buf + OFF_AH + ao);
                LDSM4(a_l[mt], buf + OFF_AL + ao);
            }
#pragma unroll
            for (int nt = 0; nt < 4; ++nt) {
                uint32_t b_h[4], b_l[4];
                const uint32_t bo =
                    ((warp_n * 64 + nt * 16) * PADW + kk * 16) * 2 + b_quad;
                LDSM4(b_h, buf + OFF_BH + bo);
                LDSM4(b_l, buf + OFF_BL + bo);
#pragma unroll
                for (int mt = 0; mt < 4; ++mt) {
                    MMA(acc[mt][2*nt],   a_h[mt], b_h[0], b_h[1]);
                    MMA(acc[mt][2*nt+1], a_h[mt], b_h[2], b_h[3]);
                    MMA(acc[mt][2*nt],   a_h[mt], b_l[0], b_l[1]);
                    MMA(acc[mt][2*nt+1], a_h[mt], b_l[2], b_l[3]);
                    MMA(acc[mt][2*nt],   a_l[mt], b_h[0], b_h[1]);
                    MMA(acc[mt][2*nt+1], a_l[mt], b_h[2], b_h[3]);
                }
            }
        }
    }

    // -------------------- epilogue --------------------
    const int l4 = lid >> 2;
    const int l2 = (lid & 3) * 2;
#pragma unroll
    for (int mt = 0; mt < 4; ++mt) {
#pragma unroll
        for (int nt = 0; nt < 8; ++nt) {
#pragma unroll
            for (int h = 0; h < 2; ++h) {
                const long long R = row0 + warp_m * 64 + mt * 16 + h * 8 + l4;
                const int C = col0 + warp_n * 64 + nt * 8 + l2;
                float v0 = acc[mt][nt][h * 2 + 0];
                float v1 = acc[mt][nt][h * 2 + 1];
                if (mode == 0) {
                    if (residual) {
                        const float* Ro = residual + z * sR + R * ldc + C;
                        v0 += Ro[0];
                        v1 += Ro[1];
                    }
                    float2 o = make_float2(v0, v1);
                    *reinterpret_cast<float2*>(outF + z * sC + R * ldc + C) = o;
                } else if (mode == 1) {
                    v0 += bias[C];
                    v1 += bias[C + 1];
                    __nv_bfloat16 h0 = __float2bfloat16(v0);
                    __nv_bfloat16 h1 = __float2bfloat16(v1);
                    __nv_bfloat16 l0 = __float2bfloat16(v0 - __bfloat162float(h0));
                    __nv_bfloat16 l1 = __float2bfloat16(v1 - __bfloat162float(h1));
                    *reinterpret_cast<__nv_bfloat162*>(outH + R * ldc + C) =
                        __halves2bfloat162(h0, h1);
                    *reinterpret_cast<__nv_bfloat162*>(outL + R * ldc + C) =
                        __halves2bfloat162(l0, l1);
                } else {
                    v0 += bias[C];
                    v1 += bias[C + 1];
                    const long long b = R >> 11;
                    const int s = (int)(R & (SS - 1));
                    __nv_bfloat16 h0 = __float2bfloat16(v0);
                    __nv_bfloat16 h1 = __float2bfloat16(v1);
                    __nv_bfloat16 l0 = __float2bfloat16(v0 - __bfloat162float(h0));
                    __nv_bfloat16 l1 = __float2bfloat16(v1 - __bfloat162float(h1));
                    long long a0 = (b * FF + C) * (long long)SS + s;
                    long long a1 = (b * FF + C + 1) * (long long)SS + s;
                    outH[a0] = h0; outL[a0] = l0;
                    outH[a1] = h1; outL[a1] = l1;
                }
            }
        }
    }
}

// ---------------------------------------------------------------------------
// Row softmax (fp32 in) -> hi/lo bf16 out. One CTA per row of 2048.
// ---------------------------------------------------------------------------
__global__ __launch_bounds__(256) void softmax_split_kernel(
    const float* __restrict__ attn,
    __nv_bfloat16* __restrict__ oh, __nv_bfloat16* __restrict__ ol)
{
    __shared__ float red[8];
    const long long row = blockIdx.x;
    const float* p = attn + row * (long long)SS;
    const int tid = threadIdx.x;

    float vals[8];
    float lmax = -1e30f;
#pragma unroll
    for (int i = 0; i < 8; i++) {
        vals[i] = p[tid + i * 256];
        lmax = fmaxf(lmax, vals[i]);
    }
#pragma unroll
    for (int o = 16; o > 0; o >>= 1)
        lmax = fmaxf(lmax, __shfl_xor_sync(0xffffffffu, lmax, o));
    if ((tid & 31) == 0) red[tid >> 5] = lmax;
    __syncthreads();
    float bmax = red[0];
#pragma unroll
    for (int w = 1; w < 8; w++) bmax = fmaxf(bmax, red[w]);
    __syncthreads();

    float lsum = 0.f;
#pragma unroll
    for (int i = 0; i < 8; i++) {
        vals[i] = __expf(vals[i] - bmax);
        lsum += vals[i];
    }
#pragma unroll
    for (int o = 16; o > 0; o >>= 1)
        lsum += __shfl_xor_sync(0xffffffffu, lsum, o);
    if ((tid & 31) == 0) red[tid >> 5] = lsum;
    __syncthreads();
    float total = 0.f;
#pragma unroll
    for (int w = 0; w < 8; w++) total += red[w];
    float inv = 1.0f / total;

#pragma unroll
    for (int i = 0; i < 8; i++) {
        float w = vals[i] * inv;
        __nv_bfloat16 h = __float2bfloat16(w);
        __nv_bfloat16 l = __float2bfloat16(w - __bfloat162float(h));
        oh[row * (long long)SS + tid + i * 256] = h;
        ol[row * (long long)SS + tid + i * 256] = l;
    }
}

// ---------------------------------------------------------------------------
// Launch
// ---------------------------------------------------------------------------
extern "C" void kernel_launch(void* const* d_in, const int* in_sizes, int n_in,
                              void* d_out, int out_size)
{
    (void)in_sizes; (void)n_in; (void)out_size;
    const float* q  = (const float*)d_in[0];
    const float* k  = (const float*)d_in[1];
    const float* v  = (const float*)d_in[2];
    const float* Wq = (const float*)d_in[3];
    const float* bq = (const float*)d_in[4];
    const float* Wk = (const float*)d_in[5];
    const float* bk = (const float*)d_in[6];
    const float* Wv = (const float*)d_in[7];
    const float* bv = (const float*)d_in[8];
    float* out = (float*)d_out;

    __nv_bfloat16 *qh,*ql,*kh,*kl,*vh,*vl, *wqh,*wql,*wkh,*wkl,*wvh,*wvl;
    __nv_bfloat16 *qph,*qpl,*kph,*kpl,*vpth,*vptl, *ath,*atl;
    float *attn;
    cudaGetSymbolAddress((void**)&qh,  g_qh);   cudaGetSymbolAddress((void**)&ql,  g_ql);
    cudaGetSymbolAddress((void**)&kh,  g_kh);   cudaGetSymbolAddress((void**)&kl,  g_kl);
    cudaGetSymbolAddress((void**)&vh,  g_vh);   cudaGetSymbolAddress((void**)&vl,  g_vl);
    cudaGetSymbolAddress((void**)&wqh, g_wqh);  cudaGetSymbolAddress((void**)&wql, g_wql);
    cudaGetSymbolAddress((void**)&wkh, g_wkh);  cudaGetSymbolAddress((void**)&wkl, g_wkl);
    cudaGetSymbolAddress((void**)&wvh, g_wvh);  cudaGetSymbolAddress((void**)&wvl, g_wvl);
    cudaGetSymbolAddress((void**)&qph, g_qph);  cudaGetSymbolAddress((void**)&qpl, g_qpl);
    cudaGetSymbolAddress((void**)&kph, g_kph);  cudaGetSymbolAddress((void**)&kpl, g_kpl);
    cudaGetSymbolAddress((void**)&vpth, g_vpth); cudaGetSymbolAddress((void**)&vptl, g_vptl);
    cudaGetSymbolAddress((void**)&attn, g_attn);
    cudaGetSymbolAddress((void**)&ath, g_ath);  cudaGetSymbolAddress((void**)&atl, g_atl);

    cudaFuncSetAttribute(gemm_mma_kernel,
                         cudaFuncAttributeMaxDynamicSharedMemorySize, SMEMB);

    // 1) split inputs
    const int nQ4 = BS * FF / 4;
    const int nW4 = FF * FF / 4;
    split_kernel<<<nQ4 / 256, 256>>>(q, qh, ql, nQ4);
    split_kernel<<<nQ4 / 256, 256>>>(k, kh, kl, nQ4);
    split_kernel<<<nQ4 / 256, 256>>>(v, vh, vl, nQ4);
    split_kernel<<<nW4 / 256, 256>>>(Wq, wqh, wql, nW4);
    split_kernel<<<nW4 / 256, 256>>>(Wk, wkh, wkl, nW4);
    split_kernel<<<nW4 / 256, 256>>>(Wv, wvh, wvl, nW4);

    dim3 blk(128);

    // 2) projections: [BS,FF] = [BS,FF] @ [FF,FF]^T + bias
    dim3 gproj(FF / 128, BS / 128, 1);
    gemm_mma_kernel<<<gproj, blk, SMEMB>>>(
        qh, ql, wqh, wql, FF, 0, 0, bq, nullptr, 0,
        nullptr, 0, FF, qph, qpl, 1);
    gemm_mma_kernel<<<gproj, blk, SMEMB>>>(
        kh, kl, wkh, wkl, FF, 0, 0, bk, nullptr, 0,
        nullptr, 0, FF, kph, kpl, 1);
    gemm_mma_kernel<<<gproj, blk, SMEMB>>>(
        vh, vl, wvh, wvl, FF, 0, 0, bv, nullptr, 0,
        nullptr, 0, FF, vpth, vptl, 2);

    // 3) logits: per batch [SS,SS] = qp @ kp^T (fp32 out)
    dim3 glog(SS / 128, SS / 128, BB);
    gemm_mma_kernel<<<glog, blk, SMEMB>>>(
        qph, qpl, kph, kpl, FF, (long long)SS * FF, (long long)SS * FF,
        nullptr, nullptr, 0,
        attn, (long long)SS * SS, SS, nullptr, nullptr, 0);

    // 4) softmax + split
    softmax_split_kernel<<<BS, 256>>>(attn, ath, atl);

    // 5) out: per batch [SS,FF] = attn @ vpT^T + q
    dim3 gout(FF / 128, SS / 128, BB);
    gemm_mma_kernel<<<gout, blk, SMEMB>>>(
        ath, atl, vpth, vptl, SS, (long long)SS * SS, (long long)FF * SS,
        nullptr, q, (long long)SS * FF,
        out, (long long)SS * FF, FF, nullptr, nullptr, 0);
}

// round 5
// speedup vs baseline: 1.3482x; 1.3482x over previous
#include <cuda_runtime.h>
#include <cuda_fp16.h>
#include <cstdint>

#define BB 4
#define SS 2048
#define FF 1024
#define BS (BB*SS)

// ---------------------------------------------------------------------------
// Scratch (static device globals — no allocation)
// ---------------------------------------------------------------------------
__device__ __align__(16) __half g_qh[BS*FF],  g_ql[BS*FF];
__device__ __align__(16) __half g_kh[BS*FF],  g_kl[BS*FF];
__device__ __align__(16) __half g_vh[BS*FF];
__device__ __align__(16) __half g_wqh[FF*FF], g_wql[FF*FF];
__device__ __align__(16) __half g_wkh[FF*FF], g_wkl[FF*FF];
__device__ __align__(16) __half g_wvh[FF*FF];
__device__ __align__(16) __half g_qph[BS*FF], g_qpl[BS*FF];
__device__ __align__(16) __half g_kph[BS*FF], g_kpl[BS*FF];
__device__ __align__(16) __half g_vpth[BS*FF];                 // vp^T [b][f][s], hi only
__device__ float g_attn[BB*SS*SS];                             // fp32 logits
__device__ __align__(16) __half g_ath[BB*SS*SS];               // softmax weights, hi only

// ---------------------------------------------------------------------------
// PTX helpers (compute_103-safe: cp.async / ldmatrix / mma.sync only)
// ---------------------------------------------------------------------------
__device__ __forceinline__ uint32_t smem_u32(const void* p) {
    uint32_t a;
    asm("{ .reg .u64 t; cvta.to.shared.u64 t, %1; cvt.u32.u64 %0, t; }"
        : "=r"(a) : "l"(p));
    return a;
}

#define CP_ASYNC16(dst, src)                                                  \
    asm volatile("cp.async.cg.shared.global [%0], [%1], 16;"                  \
                 :: "r"(dst), "l"(src))
#define CP_COMMIT() asm volatile("cp.async.commit_group;" ::: "memory")
#define CP_WAIT(n)  asm volatile("cp.async.wait_group %0;" :: "n"(n) : "memory")

#define LDSM4(R, addr)                                                        \
    asm volatile("ldmatrix.sync.aligned.m8n8.x4.shared.b16 {%0,%1,%2,%3}, [%4];" \
                 : "=r"((R)[0]), "=r"((R)[1]), "=r"((R)[2]), "=r"((R)[3])     \
                 : "r"(addr))

#define MMA(D, A, B0, B1)                                                     \
    asm volatile("mma.sync.aligned.m16n8k16.row.col.f32.f16.f16.f32 "         \
                 "{%0,%1,%2,%3}, {%4,%5,%6,%7}, {%8,%9}, {%0,%1,%2,%3};"      \
                 : "+f"((D)[0]), "+f"((D)[1]), "+f"((D)[2]), "+f"((D)[3])     \
                 : "r"((A)[0]), "r"((A)[1]), "r"((A)[2]), "r"((A)[3]),        \
                   "r"(B0), "r"(B1))

// ---------------------------------------------------------------------------
// fp32 -> fp16 hi (+ optional lo residual) split
// ---------------------------------------------------------------------------
__global__ __launch_bounds__(256) void split_kernel(
    const float* __restrict__ src,
    __half* __restrict__ hi, __half* __restrict__ lo, int n4)
{
    int i = blockIdx.x * 256 + threadIdx.x;
    if (i >= n4) return;
    float4 v = reinterpret_cast<const float4*>(src)[i];
    __half h0 = __float2half(v.x);
    __half h1 = __float2half(v.y);
    __half h2 = __float2half(v.z);
    __half h3 = __float2half(v.w);
    __half2* H = reinterpret_cast<__half2*>(hi);
    H[2*i]   = __halves2half2(h0, h1);
    H[2*i+1] = __halves2half2(h2, h3);
    if (lo) {
        __half l0 = __float2half(v.x - __half2float(h0));
        __half l1 = __float2half(v.y - __half2float(h1));
        __half l2 = __float2half(v.z - __half2float(h2));
        __half l3 = __float2half(v.w - __half2float(h3));
        __half2* L = reinterpret_cast<__half2*>(lo);
        L[2*i]   = __halves2half2(l0, l1);
        L[2*i+1] = __halves2half2(l2, l3);
    }
}

// ---------------------------------------------------------------------------
// mma.sync split-fp16 GEMM (NT): C[m,n] = sum_k A[m,k]*B[n,k]
// NPROD=3: Ah*Bh + Ah*Bl + Al*Bh (full split).  NPROD=1: Ah*Bh only.
// CTA tile 128x128, BK=32, 8 warps (4 M x 2 N), warp tile 32x64, 2 CTAs/SM.
// mode 0: outF = acc (+ residual)
// mode 1: acc + bias -> hi/lo fp16 at [m*ldc + n]
// mode 2: acc + bias -> hi fp16 transposed [(b*FF+n)*SS + s], m=b*SS+s
// ---------------------------------------------------------------------------
#define PADW   40                 // padded row length in fp16 elems (80 B)
#define TILEB  (128*PADW*2)       // 10240 B per tile

__device__ __forceinline__ void load_tile(
    uint32_t sdst, const __half* base, int r0, int K, int k0, int tid)
{
    const int ch = tid & 3;
    const int rb = tid >> 2;            // 0..63
#pragma unroll
    for (int j = 0; j < 2; ++j) {
        const int r = rb + j * 64;
        uint32_t sm = sdst + r * (PADW*2) + ch * 16;
        CP_ASYNC16(sm, base + (long long)(r0 + r) * K + k0 + ch * 8);
    }
}

template <int NPROD>
__global__ __launch_bounds__(256, 2) void gemm_mma_kernel(
    const __half* __restrict__ Ah, const __half* __restrict__ Al,
    const __half* __restrict__ Bh, const __half* __restrict__ Bl,
    int K, long long sA, long long sB,
    const float* __restrict__ bias,
    const float* __restrict__ residual, long long sR,
    float* __restrict__ outF, long long sC, int ldc,
    __half* __restrict__ outH, __half* __restrict__ outL,
    int mode)
{
    constexpr int NT = (NPROD == 3) ? 4 : 2;     // tiles per stage
    constexpr int STAGEB = NT * TILEB;
    constexpr uint32_t OFF_AH = 0;
    constexpr uint32_t OFF_AL = TILEB;                       // NPROD==3 only
    constexpr uint32_t OFF_BH = (NPROD == 3 ? 2 : 1) * TILEB;
    constexpr uint32_t OFF_BL = 3 * TILEB;                   // NPROD==3 only

    extern __shared__ char smem[];
    const uint32_t sbase = smem_u32(smem);
    const int tid = threadIdx.x;
    const int wid = tid >> 5, lid = tid & 31;
    const int warp_m = wid & 3, warp_n = wid >> 2;   // 4x2 warps, tile 32x64
    const int row0 = blockIdx.y * 128, col0 = blockIdx.x * 128;
    const long long z = blockIdx.z;

    const __half* pAh = Ah + z * sA;
    const __half* pAl = (NPROD == 3) ? (Al + z * sA) : nullptr;
    const __half* pBh = Bh + z * sB;
    const __half* pBl = (NPROD == 3) ? (Bl + z * sB) : nullptr;

    float acc[2][8][4];
#pragma unroll
    for (int t = 0; t < 2; ++t)
#pragma unroll
        for (int n = 0; n < 8; ++n)
#pragma unroll
            for (int c = 0; c < 4; ++c) acc[t][n][c] = 0.f;

    // ldmatrix lane-address components (byte offsets within a tile)
    const uint32_t a_part =
        ((warp_m * 32 + (lid & 15)) * PADW + ((lid >> 4) * 8)) * 2;
    const uint32_t b_part =
        ((warp_n * 64 + ((lid >> 4) << 3) + (lid & 7)) * PADW +
         (((lid >> 3) & 1) * 8)) * 2;

    const int iters = K >> 5;

    auto issue_stage = [&](uint32_t sdst, int k0) {
        load_tile(sdst + OFF_AH, pAh, row0, K, k0, tid);
        if (NPROD == 3) load_tile(sdst + OFF_AL, pAl, row0, K, k0, tid);
        load_tile(sdst + OFF_BH, pBh, col0, K, k0, tid);
        if (NPROD == 3) load_tile(sdst + OFF_BL, pBl, col0, K, k0, tid);
    };

    issue_stage(sbase, 0);
    CP_COMMIT();

    for (int it = 0; it < iters; ++it) {
        const uint32_t buf = (it & 1) ? (sbase + STAGEB) : sbase;
        if (it + 1 < iters) {
            const uint32_t nbuf = (it & 1) ? sbase : (sbase + STAGEB);
            issue_stage(nbuf, (it + 1) << 5);
            CP_COMMIT();
            CP_WAIT(1);
        } else {
            CP_WAIT(0);
        }
        __syncthreads();

#pragma unroll
        for (int kk = 0; kk < 2; ++kk) {
            uint32_t a_h[2][4], a_l[2][4];
#pragma unroll
            for (int t = 0; t < 2; ++t) {
                const uint32_t ao = a_part + (t * 16 * PADW + kk * 16) * 2;
                LDSM4(a_h[t], buf + OFF_AH + ao);
                if (NPROD == 3) LDSM4(a_l[t], buf + OFF_AL + ao);
            }
#pragma unroll
            for (int p = 0; p < 4; ++p) {
                uint32_t b_h[4], b_l[4];
                const uint32_t bo = b_part + (p * 16 * PADW + kk * 16) * 2;
                LDSM4(b_h, buf + OFF_BH + bo);
                if (NPROD == 3) LDSM4(b_l, buf + OFF_BL + bo);
#pragma unroll
                for (int t = 0; t < 2; ++t) {
                    MMA(acc[t][2*p],   a_h[t], b_h[0], b_h[1]);
                    MMA(acc[t][2*p+1], a_h[t], b_h[2], b_h[3]);
                    if (NPROD == 3) {
                        MMA(acc[t][2*p],   a_h[t], b_l[0], b_l[1]);
                        MMA(acc[t][2*p+1], a_h[t], b_l[2], b_l[3]);
                        MMA(acc[t][2*p],   a_l[t], b_h[0], b_h[1]);
                        MMA(acc[t][2*p+1], a_l[t], b_h[2], b_h[3]);
                    }
                }
            }
        }
        __syncthreads();
    }

    // -------------------- epilogue --------------------
    const int l4 = lid >> 2;
    const int l2 = (lid & 3) * 2;
#pragma unroll
    for (int t = 0; t < 2; ++t) {
#pragma unroll
        for (int nt = 0; nt < 8; ++nt) {
#pragma unroll
            for (int h = 0; h < 2; ++h) {
                const long long R = row0 + warp_m * 32 + t * 16 + l4 + h * 8;
                const int C = col0 + warp_n * 64 + nt * 8 + l2;
                float v0 = acc[t][nt][h * 2 + 0];
                float v1 = acc[t][nt][h * 2 + 1];
                if (mode == 0) {
                    if (residual) {
                        const float* Ro = residual + z * sR + R * ldc + C;
                        v0 += Ro[0];
                        v1 += Ro[1];
                    }
                    float2 o = make_float2(v0, v1);
                    *reinterpret_cast<float2*>(outF + z * sC + R * ldc + C) = o;
                } else if (mode == 1) {
                    v0 += bias[C];
                    v1 += bias[C + 1];
                    __half h0 = __float2half(v0);
                    __half h1 = __float2half(v1);
                    __half l0 = __float2half(v0 - __half2float(h0));
                    __half l1 = __float2half(v1 - __half2float(h1));
                    *reinterpret_cast<__half2*>(outH + R * ldc + C) =
                        __halves2half2(h0, h1);
                    *reinterpret_cast<__half2*>(outL + R * ldc + C) =
                        __halves2half2(l0, l1);
                } else {
                    v0 += bias[C];
                    v1 += bias[C + 1];
                    const long long b = R >> 11;
                    const int s = (int)(R & (SS - 1));
                    long long a0 = (b * FF + C) * (long long)SS + s;
                    long long a1 = (b * FF + C + 1) * (long long)SS + s;
                    outH[a0] = __float2half(v0);
                    outH[a1] = __float2half(v1);
                }
            }
        }
    }
}

// ---------------------------------------------------------------------------
// Row softmax (fp32 in) -> fp16 out. One CTA per row of 2048.
// ---------------------------------------------------------------------------
__global__ __launch_bounds__(256) void softmax_kernel(
    const float* __restrict__ attn, __half* __restrict__ oh)
{
    __shared__ float red[8];
    const long long row = blockIdx.x;
    const float* p = attn + row * (long long)SS;
    const int tid = threadIdx.x;

    float vals[8];
    float lmax = -1e30f;
#pragma unroll
    for (int i = 0; i < 8; i++) {
        vals[i] = p[tid + i * 256];
        lmax = fmaxf(lmax, vals[i]);
    }
#pragma unroll
    for (int o = 16; o > 0; o >>= 1)
        lmax = fmaxf(lmax, __shfl_xor_sync(0xffffffffu, lmax, o));
    if ((tid & 31) == 0) red[tid >> 5] = lmax;
    __syncthreads();
    float bmax = red[0];
#pragma unroll
    for (int w = 1; w < 8; w++) bmax = fmaxf(bmax, red[w]);
    __syncthreads();

    float lsum = 0.f;
#pragma unroll
    for (int i = 0; i < 8; i++) {
        vals[i] = __expf(vals[i] - bmax);
        lsum += vals[i];
    }
#pragma unroll
    for (int o = 16; o > 0; o >>= 1)
        lsum += __shfl_xor_sync(0xffffffffu, lsum, o);
    if ((tid & 31) == 0) red[tid >> 5] = lsum;
    __syncthreads();
    float total = 0.f;
#pragma unroll
    for (int w = 0; w < 8; w++) total += red[w];
    float inv = 1.0f / total;

#pragma unroll
    for (int i = 0; i < 8; i++)
        oh[row * (long long)SS + tid + i * 256] = __float2half(vals[i] * inv);
}

// ---------------------------------------------------------------------------
// Launch
// ---------------------------------------------------------------------------
#define SMEMB3 (2 * 4 * TILEB)   // 81920
#define SMEMB1 (2 * 2 * TILEB)   // 40960

extern "C" void kernel_launch(void* const* d_in, const int* in_sizes, int n_in,
                              void* d_out, int out_size)
{
    (void)in_sizes; (void)n_in; (void)out_size;
    const float* q  = (const float*)d_in[0];
    const float* k  = (const float*)d_in[1];
    const float* v  = (const float*)d_in[2];
    const float* Wq = (const float*)d_in[3];
    const float* bq = (const float*)d_in[4];
    const float* Wk = (const float*)d_in[5];
    const float* bk = (const float*)d_in[6];
    const float* Wv = (const float*)d_in[7];
    const float* bv = (const float*)d_in[8];
    float* out = (float*)d_out;

    __half *qh,*ql,*kh,*kl,*vh, *wqh,*wql,*wkh,*wkl,*wvh;
    __half *qph,*qpl,*kph,*kpl,*vpth, *ath;
    float *attn;
    cudaGetSymbolAddress((void**)&qh,  g_qh);   cudaGetSymbolAddress((void**)&ql,  g_ql);
    cudaGetSymbolAddress((void**)&kh,  g_kh);   cudaGetSymbolAddress((void**)&kl,  g_kl);
    cudaGetSymbolAddress((void**)&vh,  g_vh);
    cudaGetSymbolAddress((void**)&wqh, g_wqh);  cudaGetSymbolAddress((void**)&wql, g_wql);
    cudaGetSymbolAddress((void**)&wkh, g_wkh);  cudaGetSymbolAddress((void**)&wkl, g_wkl);
    cudaGetSymbolAddress((void**)&wvh, g_wvh);
    cudaGetSymbolAddress((void**)&qph, g_qph);  cudaGetSymbolAddress((void**)&qpl, g_qpl);
    cudaGetSymbolAddress((void**)&kph, g_kph);  cudaGetSymbolAddress((void**)&kpl, g_kpl);
    cudaGetSymbolAddress((void**)&vpth, g_vpth);
    cudaGetSymbolAddress((void**)&attn, g_attn);
    cudaGetSymbolAddress((void**)&ath, g_ath);

    cudaFuncSetAttribute(gemm_mma_kernel<3>,
                         cudaFuncAttributeMaxDynamicSharedMemorySize, SMEMB3);
    cudaFuncSetAttribute(gemm_mma_kernel<1>,
                         cudaFuncAttributeMaxDynamicSharedMemorySize, SMEMB1);

    // 1) split inputs (v / Wv: hi only)
    const int nQ4 = BS * FF / 4;
    const int nW4 = FF * FF / 4;
    split_kernel<<<nQ4 / 256, 256>>>(q, qh, ql, nQ4);
    split_kernel<<<nQ4 / 256, 256>>>(k, kh, kl, nQ4);
    split_kernel<<<nQ4 / 256, 256>>>(v, vh, nullptr, nQ4);
    split_kernel<<<nW4 / 256, 256>>>(Wq, wqh, wql, nW4);
    split_kernel<<<nW4 / 256, 256>>>(Wk, wkh, wkl, nW4);
    split_kernel<<<nW4 / 256, 256>>>(Wv, wvh, nullptr, nW4);

    dim3 blk(256);

    // 2) projections: [BS,FF] = [BS,FF] @ [FF,FF]^T + bias
    dim3 gproj(FF / 128, BS / 128, 1);
    gemm_mma_kernel<3><<<gproj, blk, SMEMB3>>>(
        qh, ql, wqh, wql, FF, 0, 0, bq, nullptr, 0,
        nullptr, 0, FF, qph, qpl, 1);
    gemm_mma_kernel<3><<<gproj, blk, SMEMB3>>>(
        kh, kl, wkh, wkl, FF, 0, 0, bk, nullptr, 0,
        nullptr, 0, FF, kph, kpl, 1);
    gemm_mma_kernel<1><<<gproj, blk, SMEMB1>>>(
        vh, nullptr, wvh, nullptr, FF, 0, 0, bv, nullptr, 0,
        nullptr, 0, FF, vpth, nullptr, 2);

    // 3) logits: per batch [SS,SS] = qp @ kp^T (fp32 out)
    dim3 glog(SS / 128, SS / 128, BB);
    gemm_mma_kernel<3><<<glog, blk, SMEMB3>>>(
        qph, qpl, kph, kpl, FF, (long long)SS * FF, (long long)SS * FF,
        nullptr, nullptr, 0,
        attn, (long long)SS * SS, SS, nullptr, nullptr, 0);

    // 4) softmax -> fp16 weights
    softmax_kernel<<<BS, 256>>>(attn, ath);

    // 5) out: per batch [SS,FF] = attn @ vpT^T + q
    dim3 gout(FF / 128, SS / 128, BB);
    gemm_mma_kernel<1><<<gout, blk, SMEMB1>>>(
        ath, nullptr, vpth, nullptr, SS, (long long)SS * SS, (long long)FF * SS,
        nullptr, q, (long long)SS * FF,
        out, (long long)SS * FF, FF, nullptr, nullptr, 0);
}